// round 9
// baseline (speedup 1.0000x reference)
#include <cuda_runtime.h>
#include <cuda_bf16.h>
#include <cstdint>
#include <math.h>

#define SEQ_LEN 20
#define NF      812
#define HID     400
#define VARIDX  811
#define BATCH   8192
#define NGATE   (4*HID)
#define NPCOL   1664        // 13 blocks of 128 packed cols
#define VW      832         // values K width (26 chunks of 32); VARIDX zeroed, no mask
#define HW      416         // h K width (13 chunks of 32)
#define NCHP    26
#define NCHS    13
#define ABYTES  (128*80)    // 10240: 128 rows x 80B (32 bf16 + pad)
#define BUFB    (2*ABYTES)  // A + B = 20480
#define SMEMSZ  (4*BUFB)    // 4-stage = 81920

// ---------------- device scratch ----------------
__device__ float g_c[BATCH*HID];
__device__ __nv_bfloat16 g_hbf[2][BATCH*HW];       // decayed h bf16 (GEMM A), ping-pong
__device__ __nv_bfloat16 g_vbf[(size_t)SEQ_LEN*BATCH*VW];
__device__ __nv_bfloat16 g_Wv[(size_t)NPCOL*VW];   // input weights, packed cols
__device__ __nv_bfloat16 g_Whh[(size_t)NPCOL*HW];  // recurrent weights
__device__ float g_W811[NPCOL];                    // W_ih[:,VARIDX] per packed col
__device__ float g_Wmask[NPCOL];                   // W_ih[:,812]
__device__ float g_biasP[NPCOL];                   // b_ih+b_hh per packed col
__device__ __nv_bfloat16 G_pre[(size_t)SEQ_LEN*BATCH*NPCOL];  // precomputed input gates
__device__ float g_xvar[BATCH];
__device__ float g_wsum[HID];
__device__ float g_numbuf[SEQ_LEN][BATCH];
__device__ float g_denbuf[SEQ_LEN][BATCH];
__device__ float g_stepw[SEQ_LEN];

// ---------------- helpers ----------------
__device__ __forceinline__ uint32_t smem_u32(const void* p) {
    uint32_t a;
    asm("{ .reg .u64 t; cvta.to.shared.u64 t, %1; cvt.u32.u64 %0, t; }" : "=r"(a) : "l"(p));
    return a;
}
__device__ __forceinline__ void cp16(uint32_t dst, const void* src) {
    asm volatile("cp.async.cg.shared.global [%0], [%1], 16;" :: "r"(dst), "l"(src));
}
__device__ __forceinline__ void ldsm4(uint32_t& r0, uint32_t& r1, uint32_t& r2, uint32_t& r3,
                                      uint32_t addr) {
    asm volatile("ldmatrix.sync.aligned.m8n8.x4.shared.b16 {%0,%1,%2,%3}, [%4];"
        : "=r"(r0), "=r"(r1), "=r"(r2), "=r"(r3) : "r"(addr));
}
__device__ __forceinline__ void mma_bf16(float* c, uint32_t a0, uint32_t a1, uint32_t a2, uint32_t a3,
                                         uint32_t b0, uint32_t b1) {
    asm volatile("mma.sync.aligned.m16n8k16.row.col.f32.bf16.bf16.f32 "
        "{%0,%1,%2,%3}, {%4,%5,%6,%7}, {%8,%9}, {%0,%1,%2,%3};"
        : "+f"(c[0]), "+f"(c[1]), "+f"(c[2]), "+f"(c[3])
        : "r"(a0), "r"(a1), "r"(a2), "r"(a3), "r"(b0), "r"(b1));
}
__device__ __forceinline__ float bf2f(__nv_bfloat16 x) { return __bfloat162float(x); }

// ---------------- init ----------------
__global__ void k_init(const float* __restrict__ W_decay) {
    int idx = blockIdx.x*blockDim.x + threadIdx.x;
    if (idx < BATCH*HW) {
        g_hbf[0][idx] = __float2bfloat16(0.f);
        g_hbf[1][idx] = __float2bfloat16(0.f);
    }
    if (idx < BATCH*HID) g_c[idx] = 0.f;
    if (idx < HID) {
        const float* row = W_decay + (size_t)idx*NF;
        float s = 0.f;
        for (int f = 0; f < NF; f++) s += row[f];
        g_wsum[idx] = s;
    }
}

// ---------------- prepack values to bf16 time-major (VARIDX zeroed, no mask) ----------------
__global__ void k_vpack(const float* __restrict__ values) {
    size_t idx = (size_t)blockIdx.x*blockDim.x + threadIdx.x;
    if (idx >= (size_t)SEQ_LEN*BATCH*VW) return;
    int v = idx % VW;
    size_t r = idx / VW;
    int b = r % BATCH, t = r / BATCH;
    float x = 0.f;
    if (v < NF && v != VARIDX) x = values[((size_t)b*SEQ_LEN + t)*NF + v];
    g_vbf[idx] = __float2bfloat16(x);
}

// ---------------- pack weights (fragment-epilogue-friendly permutation) ----------------
__global__ void k_pack(const float* __restrict__ W_ih, const float* __restrict__ W_hh,
                       const float* __restrict__ b_ih, const float* __restrict__ b_hh) {
    size_t idx = (size_t)blockIdx.x*blockDim.x + threadIdx.x;
    if (idx >= (size_t)NPCOL*VW) return;
    int p = idx / VW, k = idx % VW;
    int colBlk = p >> 7, pb = p & 127;
    int wn = pb >> 6, rr = pb & 63, nf = rr >> 3, c = rr & 7;
    int gate = nf >> 1, sb = nf & 1;
    int unit = colBlk*32 + wn*16 + sb*8 + c;
    bool valid = (unit < HID);
    int orig = gate*HID + unit;
    float wv = (valid && k < NF) ? W_ih[(size_t)orig*(NF+1) + k] : 0.f;
    g_Wv[idx] = __float2bfloat16(wv);
    if (k < HW) {
        float wh = (valid && k < HID) ? W_hh[(size_t)orig*HID + k] : 0.f;
        g_Whh[(size_t)p*HW + k] = __float2bfloat16(wh);
    }
    if (k == 0) {
        g_W811[p]  = valid ? W_ih[(size_t)orig*(NF+1) + VARIDX] : 0.f;
        g_Wmask[p] = valid ? W_ih[(size_t)orig*(NF+1) + NF]     : 0.f;
        g_biasP[p] = valid ? (b_ih[orig] + b_hh[orig])          : 0.f;
    }
}

// ---------------- per-step xh dot + imputation + loss contribs ----------------
__global__ void __launch_bounds__(256) k_xh(
    const float* __restrict__ values, const float* __restrict__ masks,
    const float* __restrict__ W_reg, const float* __restrict__ b_reg,
    float* __restrict__ out_imp, int t)
{
    int warp = threadIdx.x >> 5, lane = threadIdx.x & 31;
    int b = blockIdx.x*8 + warp;
    const __nv_bfloat16* h = g_hbf[t & 1] + (size_t)b*HW;
    float dot = 0.f;
    #pragma unroll
    for (int jj = 0; jj < HID; jj += 32) {
        int j = jj + lane;
        if (j < HID) dot += bf2f(h[j]) * W_reg[j];
    }
    #pragma unroll
    for (int o = 16; o > 0; o >>= 1) dot += __shfl_down_sync(0xffffffffu, dot, o);
    if (lane == 0) {
        float m = masks[b*SEQ_LEN + t];
        float xh = dot + b_reg[0];
        float xo = values[((size_t)b*SEQ_LEN + t)*NF + VARIDX];
        float xv = xo*m + (1.f - m)*xh;
        g_xvar[b] = xv;
        out_imp[b*SEQ_LEN + t] = xv;
        g_numbuf[t][b] = m * fabsf(xo - xh);
        g_denbuf[t][b] = m;
    }
}

// ---------------- generic chunk issue ----------------
__device__ __forceinline__ void issue_chunk_g(int kt, uint32_t sdst,
                                              const __nv_bfloat16* Abase, int aw,
                                              const __nv_bfloat16* Bbase, int bw,
                                              int tid) {
    #pragma unroll
    for (int i = 0; i < 2; i++) {
        int idx = i*256 + tid, row = idx >> 2, c4 = idx & 3;
        cp16(sdst + (uint32_t)(row*80 + c4*16), Abase + (size_t)row*aw + kt*32 + c4*8);
    }
    #pragma unroll
    for (int i = 0; i < 2; i++) {
        int idx = i*256 + tid, col = idx >> 2, c4 = idx & 3;
        cp16(sdst + (uint32_t)ABYTES + (uint32_t)(col*80 + c4*16),
             Bbase + (size_t)col*bw + kt*32 + c4*8);
    }
    asm volatile("cp.async.commit_group;" ::: "memory");
}

// ---------------- shared MMA mainloop ----------------
#define GEMM_MAINLOOP(NCH, ABASE, AWID, BBASE, BWID)                                   \
    issue_chunk_g(0, sb + 0*BUFB, ABASE, AWID, BBASE, BWID, tid);                      \
    issue_chunk_g(1, sb + 1*BUFB, ABASE, AWID, BBASE, BWID, tid);                      \
    issue_chunk_g(2, sb + 2*BUFB, ABASE, AWID, BBASE, BWID, tid);                      \
    _Pragma("unroll 1")                                                                \
    for (int kt = 0; kt < (NCH); kt++) {                                               \
        int buf = kt & 3;                                                              \
        if (kt < (NCH)-2)       asm volatile("cp.async.wait_group 2;" ::: "memory");   \
        else if (kt == (NCH)-2) asm volatile("cp.async.wait_group 1;" ::: "memory");   \
        else                    asm volatile("cp.async.wait_group 0;" ::: "memory");   \
        __syncthreads();                                                               \
        if (kt + 3 < (NCH))                                                            \
            issue_chunk_g(kt+3, sb + (uint32_t)(((kt+3)&3)*BUFB), ABASE, AWID, BBASE, BWID, tid); \
        uint32_t ab = aAddr + (uint32_t)(buf*BUFB);                                    \
        uint32_t bb = bAddr + (uint32_t)(buf*BUFB);                                    \
        _Pragma("unroll")                                                              \
        for (int s = 0; s < 2; s++) {                                                  \
            uint32_t a[2][4];                                                          \
            _Pragma("unroll")                                                          \
            for (int mi = 0; mi < 2; mi++)                                             \
                ldsm4(a[mi][0], a[mi][1], a[mi][2], a[mi][3], ab + mi*1280 + s*32);    \
            _Pragma("unroll")                                                          \
            for (int nfp = 0; nfp < 4; nfp++) {                                        \
                uint32_t b0, b1, b2, b3;                                               \
                ldsm4(b0, b1, b2, b3, bb + nfp*1280 + s*32);                           \
                _Pragma("unroll")                                                      \
                for (int mi = 0; mi < 2; mi++) {                                       \
                    mma_bf16(acc[mi][nfp*2+0], a[mi][0], a[mi][1], a[mi][2], a[mi][3], b0, b2); \
                    mma_bf16(acc[mi][nfp*2+1], a[mi][0], a[mi][1], a[mi][2], a[mi][3], b1, b3); \
                }                                                                      \
            }                                                                          \
        }                                                                              \
    }

// ---------------- precompute GEMM: G_pre = Xall @ Wv^T + bias + m*Wmask ----------------
__global__ void __launch_bounds__(256, 2) k_pre(const float* __restrict__ masks)
{
    extern __shared__ char smem[];
    uint32_t sb = smem_u32(smem);
    int tid = threadIdx.x;
    int warp = tid >> 5, lane = tid & 31, q = lane & 3, rq = lane >> 2;
    int wm = warp & 3, wn = warp >> 2;
    int rowBase = blockIdx.y * 128;       // global row in 0..163839
    int colBlk = blockIdx.x;

    int l8 = lane & 7, lb = (lane >> 3) & 1, lh = lane >> 4;
    uint32_t aAddr = sb + (uint32_t)((wm*32 + l8 + lb*8)*80 + lh*16);
    uint32_t bAddr = sb + (uint32_t)(ABYTES + (wn*64 + l8 + lb*8)*80 + lh*16);

    float acc[2][8][4];
    #pragma unroll
    for (int mi = 0; mi < 2; mi++)
        #pragma unroll
        for (int nf = 0; nf < 8; nf++)
            #pragma unroll
            for (int j = 0; j < 4; j++) acc[mi][nf][j] = 0.f;

    const __nv_bfloat16* Ab = g_vbf + (size_t)rowBase*VW;
    const __nv_bfloat16* Bb = g_Wv + (size_t)(colBlk*128)*VW;
    GEMM_MAINLOOP(NCHP, Ab, VW, Bb, VW)

    // epilogue: + bias + m*Wmask, store bf16
    int colBase = colBlk*128 + wn*64;
    int row0 = rowBase + wm*32 + rq;
    #pragma unroll
    for (int mi = 0; mi < 2; mi++) {
        #pragma unroll
        for (int r = 0; r < 2; r++) {
            int row = row0 + mi*16 + r*8;
            int b = row & (BATCH-1), t = row >> 13;
            float m = masks[b*SEQ_LEN + t];
            int e = r*2;
            #pragma unroll
            for (int nf = 0; nf < 8; nf++) {
                int col = colBase + nf*8 + 2*q;
                float2 bi = *(const float2*)&g_biasP[col];
                float2 wm2 = *(const float2*)&g_Wmask[col];
                __nv_bfloat162 o;
                o.x = __float2bfloat16(acc[mi][nf][e]   + bi.x + m*wm2.x);
                o.y = __float2bfloat16(acc[mi][nf][e+1] + bi.y + m*wm2.y);
                *(__nv_bfloat162*)&G_pre[(size_t)row*NPCOL + col] = o;
            }
        }
    }
}

// ---------------- per-step GEMM (K=416) + G_pre + rank-1 xvar + LSTM + decay(t+1) ----------------
__global__ void __launch_bounds__(256, 2) k_step(
    const float* __restrict__ deltas, const float* __restrict__ b_decay, int t)
{
    extern __shared__ char smem[];
    uint32_t sb = smem_u32(smem);
    int tid = threadIdx.x;
    int warp = tid >> 5, lane = tid & 31, q = lane & 3, rq = lane >> 2;
    int wm = warp & 3, wn = warp >> 2;
    int rowBase = blockIdx.y * 128;
    int colBlk = blockIdx.x;
    __nv_bfloat16* hbf_out = g_hbf[(t+1) & 1];

    int l8 = lane & 7, lb = (lane >> 3) & 1, lh = lane >> 4;
    uint32_t aAddr = sb + (uint32_t)((wm*32 + l8 + lb*8)*80 + lh*16);
    uint32_t bAddr = sb + (uint32_t)(ABYTES + (wn*64 + l8 + lb*8)*80 + lh*16);

    float acc[2][8][4];
    #pragma unroll
    for (int mi = 0; mi < 2; mi++)
        #pragma unroll
        for (int nf = 0; nf < 8; nf++)
            #pragma unroll
            for (int j = 0; j < 4; j++) acc[mi][nf][j] = 0.f;

    const __nv_bfloat16* Ab = g_hbf[t & 1] + (size_t)rowBase*HW;
    const __nv_bfloat16* Bb = g_Whh + (size_t)(colBlk*128)*HW;
    GEMM_MAINLOOP(NCHS, Ab, HW, Bb, HW)

    // ---- epilogue: gates = acc + G_pre + xvar*W811 -> LSTM -> c, decayed h(t+1) ----
    const __nv_bfloat16* Gt = G_pre + (size_t)t*BATCH*NPCOL;
    int colW = colBlk*128 + wn*64;
    int row_b = rowBase + wm*32 + rq;
    bool wr_h = (t+1 < SEQ_LEN);
    #pragma unroll
    for (int sbx = 0; sbx < 2; sbx++) {
        int u0 = colBlk*32 + wn*16 + sbx*8 + 2*q;
        if (u0 >= HID) continue;
        float2 ws = *(const float2*)&g_wsum[u0];
        float2 bd = *(const float2*)&b_decay[u0];
        float2 w8i = *(const float2*)&g_W811[colW + (0+sbx)*8 + 2*q];
        float2 w8f = *(const float2*)&g_W811[colW + (2+sbx)*8 + 2*q];
        float2 w8g = *(const float2*)&g_W811[colW + (4+sbx)*8 + 2*q];
        float2 w8o = *(const float2*)&g_W811[colW + (6+sbx)*8 + 2*q];
        #pragma unroll
        for (int mi = 0; mi < 2; mi++) {
            #pragma unroll
            for (int r = 0; r < 2; r++) {
                int row = row_b + mi*16 + r*8;
                float xv = g_xvar[row];
                size_t gbase = (size_t)row*NPCOL + colW;
                __nv_bfloat162 Gi = *(const __nv_bfloat162*)&Gt[gbase + (0+sbx)*8 + 2*q];
                __nv_bfloat162 Gf = *(const __nv_bfloat162*)&Gt[gbase + (2+sbx)*8 + 2*q];
                __nv_bfloat162 Gg = *(const __nv_bfloat162*)&Gt[gbase + (4+sbx)*8 + 2*q];
                __nv_bfloat162 Go = *(const __nv_bfloat162*)&Gt[gbase + (6+sbx)*8 + 2*q];
                int e = r*2;
                float ig0 = acc[mi][0+sbx][e]   + bf2f(Gi.x) + xv*w8i.x;
                float ig1 = acc[mi][0+sbx][e+1] + bf2f(Gi.y) + xv*w8i.y;
                float fg0 = acc[mi][2+sbx][e]   + bf2f(Gf.x) + xv*w8f.x;
                float fg1 = acc[mi][2+sbx][e+1] + bf2f(Gf.y) + xv*w8f.y;
                float gg0 = acc[mi][4+sbx][e]   + bf2f(Gg.x) + xv*w8g.x;
                float gg1 = acc[mi][4+sbx][e+1] + bf2f(Gg.y) + xv*w8g.y;
                float og0 = acc[mi][6+sbx][e]   + bf2f(Go.x) + xv*w8o.x;
                float og1 = acc[mi][6+sbx][e+1] + bf2f(Go.y) + xv*w8o.y;
                float2 cin = *(float2*)&g_c[(size_t)row*HID + u0];
                float si0 = 1.f/(1.f + expf(-ig0)), si1 = 1.f/(1.f + expf(-ig1));
                float sf0 = 1.f/(1.f + expf(-fg0)), sf1 = 1.f/(1.f + expf(-fg1));
                float so0 = 1.f/(1.f + expf(-og0)), so1 = 1.f/(1.f + expf(-og1));
                float c0 = sf0*cin.x + si0*tanhf(gg0);
                float c1 = sf1*cin.y + si1*tanhf(gg1);
                *(float2*)&g_c[(size_t)row*HID + u0] = make_float2(c0, c1);
                float h0 = so0*tanhf(c0);
                float h1 = so1*tanhf(c1);
                if (wr_h) {   // decay for step t+1 fused here
                    float d = deltas[row*SEQ_LEN + t + 1];
                    float g0 = expf(-fmaxf(d*ws.x + bd.x, 0.f));
                    float g1 = expf(-fmaxf(d*ws.y + bd.y, 0.f));
                    __nv_bfloat162 hp;
                    hp.x = __float2bfloat16(h0*g0);
                    hp.y = __float2bfloat16(h1*g1);
                    *(__nv_bfloat162*)&hbf_out[(size_t)row*HW + u0] = hp;
                }
            }
        }
    }
}

// ---------------- deterministic loss reduction ----------------
__global__ void k_loss1() {
    int t = blockIdx.x, tid = threadIdx.x;
    float sn = 0.f, sd = 0.f;
    for (int b = tid; b < BATCH; b += 256) { sn += g_numbuf[t][b]; sd += g_denbuf[t][b]; }
    __shared__ float rn[256], rd[256];
    rn[tid] = sn; rd[tid] = sd;
    __syncthreads();
    for (int o = 128; o > 0; o >>= 1) {
        if (tid < o) { rn[tid] += rn[tid+o]; rd[tid] += rd[tid+o]; }
        __syncthreads();
    }
    if (tid == 0) g_stepw[t] = rn[0] / (rd[0] + 1e-5f);
}
__global__ void k_loss2(float* __restrict__ out) {
    if (threadIdx.x == 0 && blockIdx.x == 0) {
        float s = 0.f;
        for (int t = 0; t < SEQ_LEN; t++) s += g_stepw[t];
        out[0] = s / (float)SEQ_LEN;
    }
}

extern "C" void kernel_launch(void* const* d_in, const int* in_sizes, int n_in,
                              void* d_out, int out_size) {
    const float* values  = (const float*)d_in[0];
    const float* masks   = (const float*)d_in[1];
    const float* deltas  = (const float*)d_in[2];
    const float* W_decay = (const float*)d_in[3];
    const float* b_decay = (const float*)d_in[4];
    const float* W_reg   = (const float*)d_in[5];
    const float* b_reg   = (const float*)d_in[6];
    const float* W_ih    = (const float*)d_in[7];
    const float* W_hh    = (const float*)d_in[8];
    const float* b_ih    = (const float*)d_in[9];
    const float* b_hh    = (const float*)d_in[10];
    float* out = (float*)d_out;
    float* out_imp = out + 1;

    cudaFuncSetAttribute(k_pre,  cudaFuncAttributeMaxDynamicSharedMemorySize, SMEMSZ);
    cudaFuncSetAttribute(k_step, cudaFuncAttributeMaxDynamicSharedMemorySize, SMEMSZ);

    k_init<<<(BATCH*HW + 255)/256, 256>>>(W_decay);
    k_vpack<<<(int)(((size_t)SEQ_LEN*BATCH*VW + 255)/256), 256>>>(values);
    k_pack<<<(int)(((size_t)NPCOL*VW + 255)/256), 256>>>(W_ih, W_hh, b_ih, b_hh);

    dim3 gpre(13, (SEQ_LEN*BATCH)/128);   // (13, 1280)
    k_pre<<<gpre, 256, SMEMSZ>>>(masks);

    for (int t = 0; t < SEQ_LEN; t++) {
        k_xh<<<BATCH/8, 256>>>(values, masks, W_reg, b_reg, out_imp, t);
        dim3 grid(13, BATCH/128);         // (13, 64)
        k_step<<<grid, 256, SMEMSZ>>>(deltas, b_decay, t);
    }
    k_loss1<<<SEQ_LEN, 256>>>();
    k_loss2<<<1, 32>>>(out);
}